// round 16
// baseline (speedup 1.0000x reference)
#include <cuda_runtime.h>
#include <cuda_bf16.h>
#include <cstdint>
#include <math.h>

// ---------------- problem constants ----------------
#define BATCH   32
#define HH      56
#define WIMG    56
#define DIM     256
#define HEADS   8
#define HD      32
#define WS      7
#define SHIFT   3
#define NTOK    49
#define NWIN    64
#define HIDDEN  1024
#define T_TOK   100352

// ---------------- scratch ----------------
__device__ __nv_bfloat16 g_bufA[(size_t)T_TOK * 1024]; // qkv [T,768] / fc1-out [T,1024]
__device__ __nv_bfloat16 g_bufB[(size_t)T_TOK * 256];  // LN1-out / attn-out
__device__ __nv_bfloat16 g_bufC[(size_t)T_TOK * 256];  // LN2-out
__device__ float         g_bufX[(size_t)T_TOK * 256];  // x after first residual (fp32)
__device__ __nv_bfloat16 g_bufW[786432];               // bf16 weights: qkv|proj|fc1|fc2
__device__ float         g_comb[NWIN * HEADS * NTOK * NTOK]; // rpb-gather + mask

// ---------------- helpers ----------------
__device__ __forceinline__ uint32_t smem_u32(const void* p) {
    uint32_t a;
    asm("{ .reg .u64 t; cvta.to.shared.u64 t, %1; cvt.u32.u64 %0, t; }" : "=r"(a) : "l"(p));
    return a;
}
#define CP_ASYNC16(dst, src) \
    asm volatile("cp.async.cg.shared.global [%0], [%1], 16;\n" :: "r"(dst), "l"(src))
#define CP_COMMIT() asm volatile("cp.async.commit_group;\n" ::: "memory")
#define CP_WAIT1()  asm volatile("cp.async.wait_group 1;\n" ::: "memory")
#define CP_WAIT2()  asm volatile("cp.async.wait_group 2;\n" ::: "memory")

#define LDSM_X4(r0, r1, r2, r3, addr) \
    asm volatile("ldmatrix.sync.aligned.m8n8.x4.shared.b16 {%0,%1,%2,%3}, [%4];" \
        : "=r"(r0), "=r"(r1), "=r"(r2), "=r"(r3) : "r"(addr))

__device__ __forceinline__ void mma_bf16(float* d, const uint32_t* a, const uint32_t* b) {
    asm volatile(
        "mma.sync.aligned.m16n8k16.row.col.f32.bf16.bf16.f32 "
        "{%0,%1,%2,%3}, {%4,%5,%6,%7}, {%8,%9}, {%0,%1,%2,%3};"
        : "+f"(d[0]), "+f"(d[1]), "+f"(d[2]), "+f"(d[3])
        : "r"(a[0]), "r"(a[1]), "r"(a[2]), "r"(a[3]), "r"(b[0]), "r"(b[1]));
}

__device__ __forceinline__ uint32_t packbf(float x, float y) {
    __nv_bfloat162 h = __floats2bfloat162_rn(x, y);
    return *(uint32_t*)&h;
}

__device__ __forceinline__ int win_to_pix(int m) {
    int n_in = m % NTOK;
    int wv   = m / NTOK;
    int bimg = wv >> 6;
    int wi   = wv & 63;
    int wh   = wi >> 3;
    int wc   = wi & 7;
    int i    = n_in / WS;
    int j    = n_in - i * WS;
    int pr   = wh * WS + i + SHIFT; if (pr >= HH)   pr -= HH;
    int pc   = wc * WS + j + SHIFT; if (pc >= WIMG) pc -= WIMG;
    return bimg * (HH * WIMG) + pr * WIMG + pc;
}

// ---------------- all weights -> bf16, one kernel ----------------
__global__ void convw_kernel(const float* __restrict__ s0, const float* __restrict__ s1,
                             const float* __restrict__ s2, const float* __restrict__ s3,
                             __nv_bfloat16* __restrict__ d) {
    int i = blockIdx.x * 256 + threadIdx.x;
    if (i >= 786432) return;
    float v;
    if (i < 196608)      v = s0[i];
    else if (i < 262144) v = s1[i - 196608];
    else if (i < 524288) v = s2[i - 262144];
    else                 v = s3[i - 524288];
    d[i] = __float2bfloat16_rn(v);
}

// ---------------- combined bias table ----------------
__global__ void comb_kernel(const float* __restrict__ rpb, const int* __restrict__ relix,
                            const float* __restrict__ mask, float* __restrict__ comb) {
    int wh = blockIdx.x;
    int wi = wh >> 3, h = wh & 7;
    for (int e = threadIdx.x; e < NTOK * NTOK; e += 256)
        comb[(size_t)wh * (NTOK * NTOK) + e] =
            rpb[relix[e] * HEADS + h] + mask[(size_t)wi * (NTOK * NTOK) + e];
}

// ---------------- LayerNorm + shift + window gather, bf16 output ------------
__global__ __launch_bounds__(256) void ln_kernel(
    const float* __restrict__ x, const float* __restrict__ w,
    const float* __restrict__ b, __nv_bfloat16* __restrict__ out)
{
    int t    = blockIdx.x * 8 + (threadIdx.x >> 5);
    int lane = threadIdx.x & 31;
    int src  = win_to_pix(t);

    const float4* px = (const float4*)(x + (size_t)src * DIM) + lane * 2;
    float4 v0 = px[0], v1 = px[1];

    float s  = v0.x + v0.y + v0.z + v0.w + v1.x + v1.y + v1.z + v1.w;
    float ss = v0.x*v0.x + v0.y*v0.y + v0.z*v0.z + v0.w*v0.w
             + v1.x*v1.x + v1.y*v1.y + v1.z*v1.z + v1.w*v1.w;
    #pragma unroll
    for (int o = 16; o; o >>= 1) {
        s  += __shfl_xor_sync(0xffffffffu, s,  o);
        ss += __shfl_xor_sync(0xffffffffu, ss, o);
    }
    float mean = s * (1.0f / DIM);
    float var  = ss * (1.0f / DIM) - mean * mean;
    float rstd = rsqrtf(var + 1e-5f);

    int c0 = lane * 8;
    const float4* pw = (const float4*)(w + c0);
    const float4* pb = (const float4*)(b + c0);
    float4 w0 = pw[0], w1 = pw[1], b0 = pb[0], b1 = pb[1];

    union { __nv_bfloat162 h2[4]; uint4 u; } pk;
    pk.h2[0] = __floats2bfloat162_rn((v0.x - mean) * rstd * w0.x + b0.x,
                                     (v0.y - mean) * rstd * w0.y + b0.y);
    pk.h2[1] = __floats2bfloat162_rn((v0.z - mean) * rstd * w0.z + b0.z,
                                     (v0.w - mean) * rstd * w0.w + b0.w);
    pk.h2[2] = __floats2bfloat162_rn((v1.x - mean) * rstd * w1.x + b1.x,
                                     (v1.y - mean) * rstd * w1.y + b1.y);
    pk.h2[3] = __floats2bfloat162_rn((v1.z - mean) * rstd * w1.z + b1.z,
                                     (v1.w - mean) * rstd * w1.w + b1.w);
    *(uint4*)(out + (size_t)t * DIM + c0) = pk.u;
}

// == 256-thread GEMM, CTA 128x128, 8 warps of 64x32, BK=32, ldmatrix, occ=5 ==
#define LDW4 20                   // u32 words per 32-bf16 row (64B data + 16B pad)
#define A_W4 (128 * LDW4)         // 2560 words
#define STG4 (2 * A_W4)           // 5120 words / stage (20480B), 2 stages

template<int EPI>
__global__ __launch_bounds__(256, 5) void mgemm4_kernel(
    const __nv_bfloat16* __restrict__ A, const __nv_bfloat16* __restrict__ Bw,
    const float* __restrict__ bias, const float* __restrict__ res,
    void* __restrict__ Cv, int Nout, int K)
{
    extern __shared__ uint32_t smw[];
    int tid  = threadIdx.x;
    int wid  = tid >> 5, lane = tid & 31;
    int wm   = wid >> 2, wn = wid & 3;
    int g    = lane >> 2, t4 = lane & 3;
    int lr   = lane & 15, lc = lane >> 4;     // ldmatrix addressing
    int m0   = blockIdx.y * 128;
    int n0   = blockIdx.x * 128;
    uint32_t sbase = smem_u32(smw);

    float acc[4][4][4];
    #pragma unroll
    for (int i = 0; i < 4; ++i)
        #pragma unroll
        for (int j = 0; j < 4; ++j)
            #pragma unroll
            for (int k = 0; k < 4; ++k) acc[i][j][k] = 0.0f;

    const int T = K >> 5;   // K/32 tiles

    auto issue = [&](int kt, int s) {
        uint32_t ab = sbase + (uint32_t)(s * STG4) * 4u;
        uint32_t bb = ab + (uint32_t)A_W4 * 4u;
        int k0 = kt << 5;
        #pragma unroll
        for (int i = 0; i < 2; ++i) {
            int c = tid + i * 256;
            int row = c >> 2, cc = c & 3;
            CP_ASYNC16(ab + (uint32_t)(row * LDW4 + cc * 4) * 4u,
                       A + (size_t)(m0 + row) * K + k0 + cc * 8);
        }
        #pragma unroll
        for (int i = 0; i < 2; ++i) {
            int c = tid + i * 256;
            int row = c >> 2, cc = c & 3;
            CP_ASYNC16(bb + (uint32_t)(row * LDW4 + cc * 4) * 4u,
                       Bw + (size_t)(n0 + row) * K + k0 + cc * 8);
        }
        CP_COMMIT();
    };

    issue(0, 0); issue(1, 1);

    for (int t = 0; t < T; ++t) {
        int s = t & 1;
        CP_WAIT1();
        __syncthreads();
        uint32_t As = sbase + (uint32_t)(s * STG4) * 4u;
        uint32_t Bs = As + (uint32_t)A_W4 * 4u;

        #pragma unroll
        for (int ks = 0; ks < 2; ++ks) {
            int kw = ks * 8 + lc * 4;
            uint32_t af[4][4], bf2[4][2];
            #pragma unroll
            for (int mt = 0; mt < 4; ++mt) {
                uint32_t ad = As + (uint32_t)((wm * 64 + mt * 16 + lr) * LDW4 + kw) * 4u;
                LDSM_X4(af[mt][0], af[mt][1], af[mt][2], af[mt][3], ad);
            }
            #pragma unroll
            for (int np = 0; np < 2; ++np) {
                uint32_t bd = Bs + (uint32_t)((wn * 32 + np * 16 + lr) * LDW4 + kw) * 4u;
                LDSM_X4(bf2[2 * np][0], bf2[2 * np + 1][0],
                        bf2[2 * np][1], bf2[2 * np + 1][1], bd);
            }
            #pragma unroll
            for (int mt = 0; mt < 4; ++mt)
                #pragma unroll
                for (int nt = 0; nt < 4; ++nt)
                    mma_bf16(acc[mt][nt], af[mt], bf2[nt]);
        }
        __syncthreads();
        if (t + 2 < T) issue(t + 2, s); else CP_COMMIT();
    }

    const float kS = 0.70710678118654752440f;
    #pragma unroll
    for (int mt = 0; mt < 4; ++mt) {
        #pragma unroll
        for (int rr = 0; rr < 2; ++rr) {
            int m = m0 + wm * 64 + mt * 16 + rr * 8 + g;
            #pragma unroll
            for (int nt = 0; nt < 4; ++nt) {
                int col = wn * 32 + nt * 8 + t4 * 2;
                float v0 = acc[mt][nt][rr * 2 + 0] + bias[n0 + col];
                float v1 = acc[mt][nt][rr * 2 + 1] + bias[n0 + col + 1];
                if (EPI == 1) {
                    v0 = 0.5f * v0 * (1.0f + erff(v0 * kS));
                    v1 = 0.5f * v1 * (1.0f + erff(v1 * kS));
                }
                if (EPI == 2) {
                    const float* rrow = res + (size_t)m * Nout + n0;
                    float* crow = (float*)Cv + (size_t)m * Nout + n0;
                    *(float2*)(crow + col) = make_float2(v0 + rrow[col], v1 + rrow[col + 1]);
                } else {
                    __nv_bfloat16* crow = (__nv_bfloat16*)Cv + (size_t)m * Nout + n0;
                    *(__nv_bfloat162*)(crow + col) = __floats2bfloat162_rn(v0, v1);
                }
            }
        }
    }
}

// ===== 512-thread proj GEMM, CTA 128x256: +bias+res scatter + fused LN2 =====
#define LDTW 20
#define A_WORDS (128 * LDTW)
#define B_WORDS (256 * LDTW)
#define STAGE_WORDS (A_WORDS + B_WORDS)

__global__ __launch_bounds__(512, 1) void proj_kernel(
    const __nv_bfloat16* __restrict__ A, const __nv_bfloat16* __restrict__ Bw,
    const float* __restrict__ bias, const float* __restrict__ res,
    float* __restrict__ C, __nv_bfloat16* __restrict__ Cln,
    const float* __restrict__ lnw, const float* __restrict__ lnb)
{
    const int Nout = 256, K = 256;
    extern __shared__ uint32_t smw[];
    int tid  = threadIdx.x;
    int wid  = tid >> 5, lane = tid & 31;
    int wm   = wid >> 3, wn = wid & 7;
    int g    = lane >> 2, t4 = lane & 3;
    int m0   = blockIdx.y * 128;
    uint32_t sbase = smem_u32(smw);

    float acc[4][4][4];
    #pragma unroll
    for (int i = 0; i < 4; ++i)
        #pragma unroll
        for (int j = 0; j < 4; ++j)
            #pragma unroll
            for (int k = 0; k < 4; ++k) acc[i][j][k] = 0.0f;

    const int T = K >> 5;

    auto issue = [&](int kt, int s) {
        uint32_t ab = sbase + (uint32_t)(s * STAGE_WORDS) * 4u;
        uint32_t bb = ab + (uint32_t)A_WORDS * 4u;
        int k0 = kt << 5;
        {
            int row = tid >> 2, cc = tid & 3;
            CP_ASYNC16(ab + (uint32_t)(row * LDTW + cc * 4) * 4u,
                       A + (size_t)(m0 + row) * K + k0 + cc * 8);
        }
        #pragma unroll
        for (int i = 0; i < 2; ++i) {
            int c = tid + i * 512;
            int row = c >> 2, cc = c & 3;
            CP_ASYNC16(bb + (uint32_t)(row * LDTW + cc * 4) * 4u,
                       Bw + (size_t)row * K + k0 + cc * 8);
        }
        CP_COMMIT();
    };

    issue(0, 0); issue(1, 1); issue(2, 2);

    int s = 0;
    for (int t = 0; t < T; ++t) {
        CP_WAIT2();
        __syncthreads();
        const uint32_t* As = smw + s * STAGE_WORDS;
        const uint32_t* Bs = As + A_WORDS;

        #pragma unroll
        for (int ks = 0; ks < 2; ++ks) {
            int kw = ks * 8 + t4;
            uint32_t af[4][4], bf2[4][2];
            #pragma unroll
            for (int mt = 0; mt < 4; ++mt) {
                int r = wm * 64 + mt * 16 + g;
                af[mt][0] = As[r * LDTW + kw];
                af[mt][1] = As[(r + 8) * LDTW + kw];
                af[mt][2] = As[r * LDTW + kw + 4];
                af[mt][3] = As[(r + 8) * LDTW + kw + 4];
            }
            #pragma unroll
            for (int nt = 0; nt < 4; ++nt) {
                int n = wn * 32 + nt * 8 + g;
                bf2[nt][0] = Bs[n * LDTW + kw];
                bf2[nt][1] = Bs[n * LDTW + kw + 4];
            }
            #pragma unroll
            for (int mt = 0; mt < 4; ++mt)
                #pragma unroll
                for (int nt = 0; nt < 4; ++nt)
                    mma_bf16(acc[mt][nt], af[mt], bf2[nt]);
        }
        __syncthreads();
        if (t + 3 < T) issue(t + 3, s); else CP_COMMIT();
        if (++s == 3) s = 0;
    }

    __syncthreads();
    float2* p2      = (float2*)smw;
    float2* rowstat = ((float2*)smw) + 4096;

    #pragma unroll
    for (int mt = 0; mt < 4; ++mt) {
        #pragma unroll
        for (int rr = 0; rr < 2; ++rr) {
            int lm = wm * 64 + mt * 16 + rr * 8 + g;
            int dm = win_to_pix(m0 + lm);
            float*       xrow = C   + (size_t)dm * Nout;
            const float* rrow = res + (size_t)dm * Nout;
            float psum = 0.0f, psq = 0.0f;
            #pragma unroll
            for (int nt = 0; nt < 4; ++nt) {
                int col = wn * 32 + nt * 8 + t4 * 2;
                float v0 = acc[mt][nt][rr * 2 + 0] + bias[col]     + rrow[col];
                float v1 = acc[mt][nt][rr * 2 + 1] + bias[col + 1] + rrow[col + 1];
                acc[mt][nt][rr * 2 + 0] = v0;
                acc[mt][nt][rr * 2 + 1] = v1;
                *(float2*)(xrow + col) = make_float2(v0, v1);
                psum += v0 + v1; psq += v0 * v0 + v1 * v1;
            }
            p2[tid * 8 + mt * 2 + rr] = make_float2(psum, psq);
        }
    }
    __syncthreads();
    if (tid < 128) {
        int lm = tid;
        int lwm = lm >> 6, lmt = (lm >> 4) & 3, lrr = (lm >> 3) & 1, lg = lm & 7;
        float s1 = 0.0f, s2 = 0.0f;
        #pragma unroll
        for (int w = 0; w < 8; ++w)
            #pragma unroll
            for (int q = 0; q < 4; ++q) {
                float2 f = p2[(((lwm * 8 + w) << 5) + (lg << 2) + q) * 8 + lmt * 2 + lrr];
                s1 += f.x; s2 += f.y;
            }
        float mean = s1 * (1.0f / 256.0f);
        float var  = s2 * (1.0f / 256.0f) - mean * mean;
        rowstat[lm] = make_float2(mean, rsqrtf(var + 1e-5f));
    }
    __syncthreads();
    #pragma unroll
    for (int mt = 0; mt < 4; ++mt) {
        #pragma unroll
        for (int rr = 0; rr < 2; ++rr) {
            int lm = wm * 64 + mt * 16 + rr * 8 + g;
            float2 st = rowstat[lm];
            int dm = win_to_pix(m0 + lm);
            __nv_bfloat16* lrow = Cln + (size_t)dm * Nout;
            #pragma unroll
            for (int nt = 0; nt < 4; ++nt) {
                int col = wn * 32 + nt * 8 + t4 * 2;
                float v0 = (acc[mt][nt][rr * 2 + 0] - st.x) * st.y * lnw[col]     + lnb[col];
                float v1 = (acc[mt][nt][rr * 2 + 1] - st.x) * st.y * lnw[col + 1] + lnb[col + 1];
                *(__nv_bfloat162*)(lrow + col) = __floats2bfloat162_rn(v0, v1);
            }
        }
    }
}

// ======== MMA attention: CTA per (window,head), 4 warps, reg softmax ========
__global__ __launch_bounds__(128) void attn_kernel(
    const __nv_bfloat16* __restrict__ qkv, const float* __restrict__ comb,
    __nv_bfloat16* __restrict__ out)
{
    __shared__ uint32_t Qs[64 * 20];
    __shared__ uint32_t Ks[64 * 20];
    __shared__ uint32_t Vs[32 * 36];

    int blk  = blockIdx.x;
    int h    = blk & (HEADS - 1);
    int wv   = blk >> 3;
    int wi   = wv & (NWIN - 1);
    int tid  = threadIdx.x;
    int warp = tid >> 5, lane = tid & 31;
    int g    = lane >> 2, t4 = lane & 3;
    const float scale = 0.17677669529663688f;

    for (int i = tid; i < 64 * 20; i += 128) { Qs[i] = 0u; Ks[i] = 0u; }
    for (int i = tid; i < 32 * 36; i += 128) Vs[i] = 0u;
    __syncthreads();

    const __nv_bfloat16* base = qkv + (size_t)wv * NTOK * 768 + h * HD;
    __nv_bfloat16* Vh = (__nv_bfloat16*)Vs;
    for (int idx = tid; idx < NTOK * 16; idx += 128) {
        int n = idx >> 4, dp = idx & 15;
        const __nv_bfloat16* p = base + (size_t)n * 768 + dp * 2;
        Qs[n * 20 + dp] = *(const uint32_t*)(p);
        Ks[n * 20 + dp] = *(const uint32_t*)(p + 256);
        __nv_bfloat162 v2 = *(const __nv_bfloat162*)(p + 512);
        Vh[(dp * 2 + 0) * 72 + n] = v2.x;
        Vh[(dp * 2 + 1) * 72 + n] = v2.y;
    }
    __syncthreads();

    float p[7][4];
    #pragma unroll
    for (int j = 0; j < 7; ++j)
        #pragma unroll
        for (int e = 0; e < 4; ++e) p[j][e] = 0.0f;

    int r0 = 16 * warp + g, r1 = r0 + 8;
    #pragma unroll
    for (int ks = 0; ks < 2; ++ks) {
        int kw = ks * 8 + t4;
        uint32_t a[4];
        a[0] = Qs[r0 * 20 + kw];
        a[1] = Qs[r1 * 20 + kw];
        a[2] = Qs[r0 * 20 + kw + 4];
        a[3] = Qs[r1 * 20 + kw + 4];
        #pragma unroll
        for (int j = 0; j < 7; ++j) {
            uint32_t b[2];
            b[0] = Ks[(8 * j + g) * 20 + kw];
            b[1] = Ks[(8 * j + g) * 20 + kw + 4];
            mma_bf16(p[j], a, b);
        }
    }

    const float* cb = comb + (size_t)(wi * 8 + h) * (NTOK * NTOK);
    float mx0 = -1e30f, mx1 = -1e30f;
    #pragma unroll
    for (int j = 0; j < 7; ++j) {
        int c0 = 8 * j + 2 * t4, c1 = c0 + 1;
        p[j][0] = (r0 < NTOK && c0 < NTOK) ? p[j][0] * scale + cb[r0 * NTOK + c0] : -1e30f;
        p[j][1] = (r0 < NTOK && c1 < NTOK) ? p[j][1] * scale + cb[r0 * NTOK + c1] : -1e30f;
        p[j][2] = (r1 < NTOK && c0 < NTOK) ? p[j][2] * scale + cb[r1 * NTOK + c0] : -1e30f;
        p[j][3] = (r1 < NTOK && c1 < NTOK) ? p[j][3] * scale + cb[r1 * NTOK + c1] : -1e30f;
        mx0 = fmaxf(mx0, fmaxf(p[j][0], p[j][1]));
        mx1 = fmaxf(mx1, fmaxf(p[j][2], p[j][3]));
    }
    mx0 = fmaxf(mx0, __shfl_xor_sync(0xffffffffu, mx0, 1));
    mx0 = fmaxf(mx0, __shfl_xor_sync(0xffffffffu, mx0, 2));
    mx1 = fmaxf(mx1, __shfl_xor_sync(0xffffffffu, mx1, 1));
    mx1 = fmaxf(mx1, __shfl_xor_sync(0xffffffffu, mx1, 2));

    float s0 = 0.0f, s1 = 0.0f;
    #pragma unroll
    for (int j = 0; j < 7; ++j) {
        p[j][0] = __expf(p[j][0] - mx0); s0 += p[j][0];
        p[j][1] = __expf(p[j][1] - mx0); s0 += p[j][1];
        p[j][2] = __expf(p[j][2] - mx1); s1 += p[j][2];
        p[j][3] = __expf(p[j][3] - mx1); s1 += p[j][3];
    }
    s0 += __shfl_xor_sync(0xffffffffu, s0, 1);
    s0 += __shfl_xor_sync(0xffffffffu, s0, 2);
    s1 += __shfl_xor_sync(0xffffffffu, s1, 1);
    s1 += __shfl_xor_sync(0xffffffffu, s1, 2);
    float i0 = 1.0f / s0, i1 = 1.0f / s1;

    uint32_t ab0[7], ab1[7];
    #pragma unroll
    for (int j = 0; j < 7; ++j) {
        ab0[j] = packbf(p[j][0] * i0, p[j][1] * i0);
        ab1[j] = packbf(p[j][2] * i1, p[j][3] * i1);
    }

    float o[4][4];
    #pragma unroll
    for (int nt = 0; nt < 4; ++nt)
        #pragma unroll
        for (int e = 0; e < 4; ++e) o[nt][e] = 0.0f;

    #pragma unroll
    for (int kt = 0; kt < 4; ++kt) {
        uint32_t a[4];
        a[0] = ab0[2 * kt];
        a[1] = ab1[2 * kt];
        a[2] = (kt < 3) ? ab0[2 * kt + 1] : 0u;
        a[3] = (kt < 3) ? ab1[2 * kt + 1] : 0u;
        int kwv = t4 + 8 * kt;
        #pragma unroll
        for (int nt = 0; nt < 4; ++nt) {
            uint32_t b[2];
            b[0] = Vs[(8 * nt + g) * 36 + kwv];
            b[1] = Vs[(8 * nt + g) * 36 + kwv + 4];
            mma_bf16(o[nt], a, b);
        }
    }

    if (r0 < NTOK) {
        __nv_bfloat16* orow = out + (size_t)(wv * NTOK + r0) * DIM + h * HD + 2 * t4;
        #pragma unroll
        for (int nt = 0; nt < 4; ++nt)
            *(__nv_bfloat162*)(orow + 8 * nt) = __floats2bfloat162_rn(o[nt][0], o[nt][1]);
    }
    if (r1 < NTOK) {
        __nv_bfloat16* orow = out + (size_t)(wv * NTOK + r1) * DIM + h * HD + 2 * t4;
        #pragma unroll
        for (int nt = 0; nt < 4; ++nt)
            *(__nv_bfloat162*)(orow + 8 * nt) = __floats2bfloat162_rn(o[nt][2], o[nt][3]);
    }
}

// ---------------- launch --------------------------------------------------
extern "C" void kernel_launch(void* const* d_in, const int* in_sizes, int n_in,
                              void* d_out, int out_size) {
    const float* x     = (const float*)d_in[0];
    const float* n1w   = (const float*)d_in[1];
    const float* n1b   = (const float*)d_in[2];
    const float* qkvw  = (const float*)d_in[3];
    const float* qkvb  = (const float*)d_in[4];
    const float* rpb   = (const float*)d_in[5];
    const float* projw = (const float*)d_in[6];
    const float* projb = (const float*)d_in[7];
    const float* n2w   = (const float*)d_in[8];
    const float* n2b   = (const float*)d_in[9];
    const float* fc1w  = (const float*)d_in[10];
    const float* fc1b  = (const float*)d_in[11];
    const float* fc2w  = (const float*)d_in[12];
    const float* fc2b  = (const float*)d_in[13];
    const int*   relix = (const int*)d_in[14];
    const float* mask  = (const float*)d_in[15];
    float* out = (float*)d_out;

    __nv_bfloat16 *bufA, *bufB, *bufC, *bufW;
    float *bufX, *combp;
    cudaGetSymbolAddress((void**)&bufA, g_bufA);
    cudaGetSymbolAddress((void**)&bufB, g_bufB);
    cudaGetSymbolAddress((void**)&bufC, g_bufC);
    cudaGetSymbolAddress((void**)&bufX, g_bufX);
    cudaGetSymbolAddress((void**)&bufW, g_bufW);
    cudaGetSymbolAddress((void**)&combp, g_comb);

    __nv_bfloat16* wqkv = bufW;
    __nv_bfloat16* wprj = wqkv + 196608;
    __nv_bfloat16* wfc1 = wprj + 65536;
    __nv_bfloat16* wfc2 = wfc1 + 262144;

    const int LN_BLOCKS = T_TOK / 8;
    const int MT = T_TOK / 128;             // 784
    const int SH4  = 2 * STG4 * 4;          // 40960
    const int SHP  = 3 * STAGE_WORDS * 4;   // 92160

    cudaFuncSetAttribute(mgemm4_kernel<0>, cudaFuncAttributeMaxDynamicSharedMemorySize, SH4);
    cudaFuncSetAttribute(mgemm4_kernel<1>, cudaFuncAttributeMaxDynamicSharedMemorySize, SH4);
    cudaFuncSetAttribute(mgemm4_kernel<2>, cudaFuncAttributeMaxDynamicSharedMemorySize, SH4);
    cudaFuncSetAttribute(proj_kernel, cudaFuncAttributeMaxDynamicSharedMemorySize, SHP);

    // 0) weight conversion + combined bias table
    convw_kernel<<<(786432 + 255) / 256, 256>>>(qkvw, projw, fc1w, fc2w, bufW);
    comb_kernel<<<NWIN * HEADS, 256>>>(rpb, relix, mask, combp);

    // 1) LN1 + shift + window partition -> bufB (bf16)
    ln_kernel<<<LN_BLOCKS, 256>>>(x, n1w, n1b, bufB);

    // 2) qkv GEMM -> bufA [T,768] (bf16)
    mgemm4_kernel<0><<<dim3(768 / 128, MT), 256, SH4>>>(
        bufB, wqkv, qkvb, nullptr, bufA, 768, DIM);

    // 3) MMA attention -> bufB (bf16, window order)
    attn_kernel<<<(T_TOK / NTOK) * HEADS, 128>>>(bufA, combp, bufB);

    // 4) proj + scatter + residual + fused LN2 -> bufX (fp32), bufC (bf16)
    proj_kernel<<<dim3(1, MT), 512, SHP>>>(
        bufB, wprj, projb, x, bufX, bufC, n2w, n2b);

    // 5) fc1 + GELU -> bufA [T,1024] (bf16)
    mgemm4_kernel<1><<<dim3(HIDDEN / 128, MT), 256, SH4>>>(
        bufC, wfc1, fc1b, nullptr, bufA, HIDDEN, DIM);

    // 6) fc2 + residual -> d_out (fp32)
    mgemm4_kernel<2><<<dim3(DIM / 128, MT), 256, SH4>>>(
        bufA, wfc2, fc2b, bufX, out, DIM, HIDDEN);
}